// round 15
// baseline (speedup 1.0000x reference)
#include <cuda_runtime.h>
#include <cuda_bf16.h>
#include <math.h>

// Problem constants
#define FL        256
#define NSC       32
#define SIG_LEN   65536
#define BATCH     16
#define HALF      128

// Tiling: block = (512-t tile, batch, scale-group-of-8), 128 threads (4 warps)
#define TILE_T    512
#define NT        4
#define NS        8
#define BLOCK_THREADS 128   // 4 warps; warp w covers t [w*128, (w+1)*128)
#define WIN       (TILE_T + FL)       // 768
#define WIN_PAD   (WIN + 16)

// Input dtype flag: 0 = bf16, 1 = float32.
__device__ int g_dtype_flag;

__global__ void dtype_probe_kernel(const void* sig) {
    __shared__ int s_crazy;
    if (threadIdx.x == 0) s_crazy = 0;
    __syncthreads();
    const __nv_bfloat16* p = (const __nv_bfloat16*)sig;
    int crazy = 0;
#pragma unroll
    for (int j = 0; j < 8; j++) {
        float v = __bfloat162float(p[threadIdx.x * 8 + j]);
        float a = fabsf(v);
        if (v != v) crazy++;
        else if (a != 0.0f && (a > 64.0f || a < 9.5367431640625e-7f)) crazy++;
    }
    for (int off = 16; off > 0; off >>= 1)
        crazy += __shfl_down_sync(0xffffffffu, crazy, off);
    if ((threadIdx.x & 31) == 0) atomicAdd(&s_crazy, crazy);
    __syncthreads();
    if (threadIdx.x == 0) g_dtype_flag = (s_crazy > 200) ? 1 : 0;
}

// Packed f32x2 helpers: low = real, high = imag.
__device__ __forceinline__ unsigned long long pack_dup(float x) {
    unsigned long long r;
    asm("mov.b64 %0, {%1, %1};" : "=l"(r) : "r"(__float_as_uint(x)));
    return r;
}
__device__ __forceinline__ unsigned long long pack2(float lo, float hi) {
    unsigned long long r;
    asm("mov.b64 %0, {%1, %2};" : "=l"(r)
        : "r"(__float_as_uint(lo)), "r"(__float_as_uint(hi)));
    return r;
}
__device__ __forceinline__ unsigned long long ffma2(unsigned long long a,
                                                    unsigned long long b,
                                                    unsigned long long c) {
    unsigned long long d;
    asm("fma.rn.f32x2 %0, %1, %2, %3;" : "=l"(d) : "l"(a), "l"(b), "l"(c));
    return d;
}

// ---------------------------------------------------------------------------
// Symmetry-folded kernel, NS=8, NT=4, 128-thread CTAs (fine occupancy quantum).
//   pair k=128±d:  acc += ffma2((wr,wi), (xp+xm, xp-xm))
// ---------------------------------------------------------------------------
__global__ void __launch_bounds__(BLOCK_THREADS, 5)
morlet_kernel(const void* __restrict__ sig_raw, float* __restrict__ outf,
              long long n_sig, long long w_floats, int mode) {
    __shared__ __align__(16) float  s_sig[WIN_PAD];   // ~3 KB
    __shared__ __align__(16) float2 s_wav[128][NS];   // 8 KB, d = 0..127

    const int b     = blockIdx.y;
    const int tile0 = blockIdx.x * TILE_T;
    const int grp   = blockIdx.z;        // 0..3
    const int s0    = grp * NS;
    const long long sbase = (long long)b * SIG_LEN;
    const int dtype = g_dtype_flag;

    const float*          sigf = (const float*)sig_raw;
    const __nv_bfloat16*  sigb = (const __nv_bfloat16*)sig_raw;

    // Stage signal window (zero-padded, guarded). Padding stays zero.
    for (int i = threadIdx.x; i < WIN_PAD; i += BLOCK_THREADS) {
        int gl = tile0 - HALF + i;
        long long g = sbase + gl;
        float v = 0.0f;
        if (i < WIN && gl >= 0 && gl < SIG_LEN && g >= 0 && g < n_sig)
            v = dtype ? sigf[g] : __bfloat162float(sigb[g]);
        s_sig[i] = v;
    }

    // Coef table: w(k=128+d), d = 0..127, 8 scales. 1024 entries, 8/thread.
    const float TWO_PI_OSC = 37.69911184307752f;  // 2*pi*6
#pragma unroll
    for (int j = 0; j < 8; j++) {
        int ci = threadIdx.x * 8 + j;    // 0..1023
        int d  = ci >> 3;
        int si = ci & 7;
        float scale = (float)(s0 + si + 1);
        float t   = (float)d / scale;
        float env = expf(-0.5f * t * t);
        float ph  = TWO_PI_OSC * t / scale;
        float sn, cs;
        sincosf(ph, &sn, &cs);
        s_wav[d][si] = make_float2(env * cs, env * sn);
    }
    __syncthreads();

    const int lane = threadIdx.x & 31;
    const int wrp  = threadIdx.x >> 5;            // 0..3
    const int tloc = wrp * 128 + lane * NT;       // multiple of 4

    // d-range: r_d = 7 * scale_max, capped 127 (k=0 tap dropped, env<=3.3e-4).
    const int scale_max = s0 + NS;
    int r_d = 7 * scale_max;
    if (r_d > 127) r_d = 127;
    const int mmax = r_d >> 2;

    // Packed accumulators: (re, im) per (scale, t). 32 u64 = 64 regs.
    unsigned long long acc[NS][NT];
#pragma unroll
    for (int si = 0; si < NS; si++)
#pragma unroll
        for (int tt = 0; tt < NT; tt++) acc[si][tt] = 0ull;

    // Sliding windows: xp = s_sig[tloc+128+4m ..+8), xm = s_sig[tloc+124-4m ..+8).
    float xp[8], xm[8];
    {
        const float4 p0 = *(const float4*)&s_sig[tloc + 128];
        const float4 p1 = *(const float4*)&s_sig[tloc + 132];
        const float4 q0 = *(const float4*)&s_sig[tloc + 124];
        const float4 q1 = *(const float4*)&s_sig[tloc + 128];
        xp[0]=p0.x; xp[1]=p0.y; xp[2]=p0.z; xp[3]=p0.w;
        xp[4]=p1.x; xp[5]=p1.y; xp[6]=p1.z; xp[7]=p1.w;
        xm[0]=q0.x; xm[1]=q0.y; xm[2]=q0.z; xm[3]=q0.w;
        xm[4]=q1.x; xm[5]=q1.y; xm[6]=q1.z; xm[7]=q1.w;
    }

    // Per-(dk): 8 packed coefs (4 broadcast LDS.128), applied to 4 t.
    auto tap = [&](int d, int dk) {
        ulonglong2 c01 = *(const ulonglong2*)&s_wav[d][0];
        ulonglong2 c23 = *(const ulonglong2*)&s_wav[d][2];
        ulonglong2 c45 = *(const ulonglong2*)&s_wav[d][4];
        ulonglong2 c67 = *(const ulonglong2*)&s_wav[d][6];
        unsigned long long wq[NS] = {c01.x, c01.y, c23.x, c23.y,
                                     c45.x, c45.y, c67.x, c67.y};
#pragma unroll
        for (int tt = 0; tt < NT; tt++) {
            float a = xp[dk + tt], m = xm[4 - dk + tt];
            unsigned long long u = pack2(a + m, a - m);
#pragma unroll
            for (int si = 0; si < NS; si++)
                acc[si][tt] = ffma2(wq[si], u, acc[si][tt]);
        }
    };

    // ---- m = 0: center tap (d=0) uses u=(x,x); wi[0]=0 exactly ----
    {
        ulonglong2 c01 = *(const ulonglong2*)&s_wav[0][0];
        ulonglong2 c23 = *(const ulonglong2*)&s_wav[0][2];
        ulonglong2 c45 = *(const ulonglong2*)&s_wav[0][4];
        ulonglong2 c67 = *(const ulonglong2*)&s_wav[0][6];
        unsigned long long wq[NS] = {c01.x, c01.y, c23.x, c23.y,
                                     c45.x, c45.y, c67.x, c67.y};
#pragma unroll
        for (int tt = 0; tt < NT; tt++) {
            unsigned long long u = pack_dup(xp[tt]);
#pragma unroll
            for (int si = 0; si < NS; si++)
                acc[si][tt] = ffma2(wq[si], u, acc[si][tt]);
        }
        tap(1, 1); tap(2, 2); tap(3, 3);
    }

    // ---- m = 1..mmax: slide windows, then 4 taps ----
    for (int m = 1; m <= mmax; m++) {
        xp[0] = xp[4]; xp[1] = xp[5]; xp[2] = xp[6]; xp[3] = xp[7];
        {
            const float4 pn = *(const float4*)&s_sig[tloc + 132 + 4 * m];
            xp[4] = pn.x; xp[5] = pn.y; xp[6] = pn.z; xp[7] = pn.w;
        }
        xm[4] = xm[0]; xm[5] = xm[1]; xm[6] = xm[2]; xm[7] = xm[3];
        {
            const float4 qn = *(const float4*)&s_sig[tloc + 124 - 4 * m];
            xm[0] = qn.x; xm[1] = qn.y; xm[2] = qn.z; xm[3] = qn.w;
        }
        const int d0 = 4 * m;
        tap(d0, 0); tap(d0 + 1, 1); tap(d0 + 2, 2); tap(d0 + 3, 3);
    }

    // Store: 4 complex per scale, tglob multiple of 4 -> 16B-aligned float2s.
    const int tglob = tile0 + tloc;
#pragma unroll
    for (int si = 0; si < NS; si++) {
        long long cbase = ((long long)(b * NSC + s0 + si)) * SIG_LEN + tglob;
#pragma unroll
        for (int tt = 0; tt < NT; tt++) {
            long long c = cbase + tt;
            float re = __uint_as_float((unsigned)(acc[si][tt] & 0xffffffffull));
            float im = __uint_as_float((unsigned)(acc[si][tt] >> 32));
            if (mode) {
                long long f = 2 * c;
                if (f + 1 < w_floats)
                    *(float2*)(outf + f) = make_float2(re, im);
            } else {
                if (c < w_floats) outf[c] = re;
            }
        }
    }
}

// ---------------------------------------------------------------------------
// Launch contract. Output treated as out_size FLOATS -> no overrun possible.
// ---------------------------------------------------------------------------
extern "C" void kernel_launch(void* const* d_in, const int* in_sizes, int n_in,
                              void* d_out, int out_size) {
    const void* sig = d_in[0];
    float* outf = (float*)d_out;

    long long n_sig = (long long)in_sizes[0];
    long long structural_sig = (long long)BATCH * SIG_LEN;
    if (structural_sig < n_sig) n_sig = structural_sig;

    long long w_floats = (long long)out_size;
    long long need_interleaved = 2LL * BATCH * NSC * SIG_LEN;
    int mode = (w_floats >= need_interleaved) ? 1 : 0;

    dtype_probe_kernel<<<1, 256>>>(sig);

    dim3 grid(SIG_LEN / TILE_T, BATCH, NSC / NS);   // (128, 16, 4)
    morlet_kernel<<<grid, BLOCK_THREADS>>>(sig, outf, n_sig, w_floats, mode);
}

// round 16
// speedup vs baseline: 1.4681x; 1.4681x over previous
#include <cuda_runtime.h>
#include <cuda_bf16.h>
#include <math.h>

// Problem constants
#define FL        256
#define NSC       32
#define SIG_LEN   65536
#define BATCH     16
#define HALF      128

// Tiling: block = (1024-t tile, batch, scale-group-of-8)  [R13 config]
#define TILE_T    1024
#define NT        4
#define NS        8
#define BLOCK_THREADS 256   // 8 warps; warp w covers t [w*128, (w+1)*128)
#define WIN       (TILE_T + FL)   // 1280

// Input dtype flag: 0 = bf16, 1 = float32.
__device__ int g_dtype_flag;

__global__ void dtype_probe_kernel(const void* sig) {
    __shared__ int s_crazy;
    if (threadIdx.x == 0) s_crazy = 0;
    __syncthreads();
    const __nv_bfloat16* p = (const __nv_bfloat16*)sig;
    int crazy = 0;
#pragma unroll
    for (int j = 0; j < 8; j++) {
        float v = __bfloat162float(p[threadIdx.x * 8 + j]);
        float a = fabsf(v);
        if (v != v) crazy++;
        else if (a != 0.0f && (a > 64.0f || a < 9.5367431640625e-7f)) crazy++;
    }
    for (int off = 16; off > 0; off >>= 1)
        crazy += __shfl_down_sync(0xffffffffu, crazy, off);
    if ((threadIdx.x & 31) == 0) atomicAdd(&s_crazy, crazy);
    __syncthreads();
    if (threadIdx.x == 0) g_dtype_flag = (s_crazy > 200) ? 1 : 0;
}

// Packed f32x2 helpers: low = real, high = imag.
__device__ __forceinline__ unsigned long long pack_dup(float x) {
    unsigned long long r;
    asm("mov.b64 %0, {%1, %1};" : "=l"(r) : "r"(__float_as_uint(x)));
    return r;
}
__device__ __forceinline__ unsigned long long pack2(float lo, float hi) {
    unsigned long long r;
    asm("mov.b64 %0, {%1, %2};" : "=l"(r)
        : "r"(__float_as_uint(lo)), "r"(__float_as_uint(hi)));
    return r;
}
__device__ __forceinline__ unsigned long long ffma2(unsigned long long a,
                                                    unsigned long long b,
                                                    unsigned long long c) {
    unsigned long long d;
    asm("fma.rn.f32x2 %0, %1, %2, %3;" : "=l"(d) : "l"(a), "l"(b), "l"(c));
    return d;
}

// ---------------------------------------------------------------------------
// Symmetry-folded kernel (R13 structure), 4.5-sigma envelope truncation.
//   pair k=128±d:  acc += ffma2((wr,wi), (xp+xm, xp-xm))
// ---------------------------------------------------------------------------
__global__ void __launch_bounds__(BLOCK_THREADS)
morlet_kernel(const void* __restrict__ sig_raw, float* __restrict__ outf,
              long long n_sig, long long w_floats, int mode) {
    __shared__ __align__(16) float  s_sig[WIN];       // 5 KB
    __shared__ __align__(16) float2 s_wav[128][NS];   // 8 KB, d = 0..127

    const int b     = blockIdx.y;
    const int tile0 = blockIdx.x * TILE_T;
    const int grp   = blockIdx.z;        // 0..3
    const int s0    = grp * NS;
    const long long sbase = (long long)b * SIG_LEN;
    const int dtype = g_dtype_flag;

    const float*          sigf = (const float*)sig_raw;
    const __nv_bfloat16*  sigb = (const __nv_bfloat16*)sig_raw;

    // Stage signal window (zero-padded, guarded).
    for (int i = threadIdx.x; i < WIN; i += BLOCK_THREADS) {
        int gl = tile0 - HALF + i;
        long long g = sbase + gl;
        float v = 0.0f;
        if (gl >= 0 && gl < SIG_LEN && g >= 0 && g < n_sig)
            v = dtype ? sigf[g] : __bfloat162float(sigb[g]);
        s_sig[i] = v;
    }

    // Coef table: w(k=128+d) for d = 0..127, 8 scales. 1024 entries, 4/thread.
    const float TWO_PI_OSC = 37.69911184307752f;  // 2*pi*6
#pragma unroll
    for (int j = 0; j < 4; j++) {
        int ci = threadIdx.x * 4 + j;    // 0..1023
        int d  = ci >> 3;
        int si = ci & 7;
        float scale = (float)(s0 + si + 1);
        float t   = (float)d / scale;
        float env = expf(-0.5f * t * t);
        float ph  = TWO_PI_OSC * t / scale;
        float sn, cs;
        sincosf(ph, &sn, &cs);
        s_wav[d][si] = make_float2(env * cs, env * sn);
    }
    __syncthreads();

    const int lane = threadIdx.x & 31;
    const int wrp  = threadIdx.x >> 5;
    const int tloc = wrp * 128 + lane * NT;       // multiple of 4

    // 4.5-sigma envelope truncation: tail energy of env^2 beyond 4.5 sigma
    // ~2e-10 of total -> rel err ~1.4e-5. r_d = ceil(4.5*scale_max), cap 127.
    const int scale_max = s0 + NS;
    int r_d = (9 * scale_max + 1) / 2;
    if (r_d > 127) r_d = 127;
    const int mmax = r_d >> 2;

    // Packed accumulators: (re, im) per (scale, t).
    unsigned long long acc[NS][NT];
#pragma unroll
    for (int si = 0; si < NS; si++)
#pragma unroll
        for (int tt = 0; tt < NT; tt++) acc[si][tt] = 0ull;

    // Sliding windows: xp covers s_sig[tloc+128+4m .. +8), xm covers
    // s_sig[tloc+124-4m .. +8). Indices used: xp[dk+tt] (0..6), xm[4-dk+tt] (1..7).
    float xp[8], xm[8];
    {
        const float4 p0 = *(const float4*)&s_sig[tloc + 128];
        const float4 p1 = *(const float4*)&s_sig[tloc + 132];
        const float4 q0 = *(const float4*)&s_sig[tloc + 124];
        const float4 q1 = *(const float4*)&s_sig[tloc + 128];
        xp[0]=p0.x; xp[1]=p0.y; xp[2]=p0.z; xp[3]=p0.w;
        xp[4]=p1.x; xp[5]=p1.y; xp[6]=p1.z; xp[7]=p1.w;
        xm[0]=q0.x; xm[1]=q0.y; xm[2]=q0.z; xm[3]=q0.w;
        xm[4]=q1.x; xm[5]=q1.y; xm[6]=q1.z; xm[7]=q1.w;
    }

    // Per-(dk): load 8 packed coefs (4 broadcast LDS.128), apply to 4 t.
    auto tap = [&](int d, int dk) {
        ulonglong2 c01 = *(const ulonglong2*)&s_wav[d][0];
        ulonglong2 c23 = *(const ulonglong2*)&s_wav[d][2];
        ulonglong2 c45 = *(const ulonglong2*)&s_wav[d][4];
        ulonglong2 c67 = *(const ulonglong2*)&s_wav[d][6];
        unsigned long long wq[NS] = {c01.x, c01.y, c23.x, c23.y,
                                     c45.x, c45.y, c67.x, c67.y};
#pragma unroll
        for (int tt = 0; tt < NT; tt++) {
            float a = xp[dk + tt], m = xm[4 - dk + tt];
            unsigned long long u = pack2(a + m, a - m);
#pragma unroll
            for (int si = 0; si < NS; si++)
                acc[si][tt] = ffma2(wq[si], u, acc[si][tt]);
        }
    };

    // ---- m = 0: center tap (d=0) uses u=(x,x); wi[0]=0 exactly ----
    {
        ulonglong2 c01 = *(const ulonglong2*)&s_wav[0][0];
        ulonglong2 c23 = *(const ulonglong2*)&s_wav[0][2];
        ulonglong2 c45 = *(const ulonglong2*)&s_wav[0][4];
        ulonglong2 c67 = *(const ulonglong2*)&s_wav[0][6];
        unsigned long long wq[NS] = {c01.x, c01.y, c23.x, c23.y,
                                     c45.x, c45.y, c67.x, c67.y};
#pragma unroll
        for (int tt = 0; tt < NT; tt++) {
            unsigned long long u = pack_dup(xp[tt]);
#pragma unroll
            for (int si = 0; si < NS; si++)
                acc[si][tt] = ffma2(wq[si], u, acc[si][tt]);
        }
        tap(1, 1); tap(2, 2); tap(3, 3);
    }

    // ---- m = 1..mmax: slide windows, then 4 taps ----
    for (int m = 1; m <= mmax; m++) {
        xp[0] = xp[4]; xp[1] = xp[5]; xp[2] = xp[6]; xp[3] = xp[7];
        {
            const float4 pn = *(const float4*)&s_sig[tloc + 132 + 4 * m];
            xp[4] = pn.x; xp[5] = pn.y; xp[6] = pn.z; xp[7] = pn.w;
        }
        xm[4] = xm[0]; xm[5] = xm[1]; xm[6] = xm[2]; xm[7] = xm[3];
        {
            const float4 qn = *(const float4*)&s_sig[tloc + 124 - 4 * m];
            xm[0] = qn.x; xm[1] = qn.y; xm[2] = qn.z; xm[3] = qn.w;
        }
        const int d0 = 4 * m;
        tap(d0, 0); tap(d0 + 1, 1); tap(d0 + 2, 2); tap(d0 + 3, 3);
    }

    // Store: 4 complex per scale, tglob multiple of 4 -> aligned float2s.
    const int tglob = tile0 + tloc;
#pragma unroll
    for (int si = 0; si < NS; si++) {
        long long cbase = ((long long)(b * NSC + s0 + si)) * SIG_LEN + tglob;
#pragma unroll
        for (int tt = 0; tt < NT; tt++) {
            long long c = cbase + tt;
            float re = __uint_as_float((unsigned)(acc[si][tt] & 0xffffffffull));
            float im = __uint_as_float((unsigned)(acc[si][tt] >> 32));
            if (mode) {
                long long f = 2 * c;
                if (f + 1 < w_floats)
                    *(float2*)(outf + f) = make_float2(re, im);
            } else {
                if (c < w_floats) outf[c] = re;
            }
        }
    }
}

// ---------------------------------------------------------------------------
// Launch contract. Output treated as out_size FLOATS -> no overrun possible.
// ---------------------------------------------------------------------------
extern "C" void kernel_launch(void* const* d_in, const int* in_sizes, int n_in,
                              void* d_out, int out_size) {
    const void* sig = d_in[0];
    float* outf = (float*)d_out;

    long long n_sig = (long long)in_sizes[0];
    long long structural_sig = (long long)BATCH * SIG_LEN;
    if (structural_sig < n_sig) n_sig = structural_sig;

    long long w_floats = (long long)out_size;
    long long need_interleaved = 2LL * BATCH * NSC * SIG_LEN;
    int mode = (w_floats >= need_interleaved) ? 1 : 0;

    dtype_probe_kernel<<<1, 256>>>(sig);

    dim3 grid(SIG_LEN / TILE_T, BATCH, NSC / NS);   // (64, 16, 4)
    morlet_kernel<<<grid, BLOCK_THREADS>>>(sig, outf, n_sig, w_floats, mode);
}